// round 9
// baseline (speedup 1.0000x reference)
#include <cuda_runtime.h>
#include <cuda_fp16.h>

#define NN 50000
#define EE 800000
#define HH 64
#define BB 50
#define LL 7
#define NSCAN_BLK 49   // ceil(50000/1024)

// ---------------- scratch (device globals; no allocations) ----------------
// NOTE: g_cursor must be zero at entry to each kernel_launch call (restored by
// scatter_fix each call; zero-initialized at load).
__device__ __half  g_h0h[NN * 32];     // layer-0 h (fp16)
__device__ __half2 g_hA[NN * 32];      // hidden ping (fp16x2, scaled)
__device__ __half2 g_hB[NN * 32];      // hidden pong (fp16x2, scaled)
__device__ __half  g_z[NN * 64];       // aggregated z (fp16); C=32 uses first 32/row
__device__ int     g_rowptr[NN + 1];
__device__ int     g_rowptr2[NN + 1];
__device__ int     g_cursor[NN];
__device__ int     g_rank[EE];
__device__ int     g_csr[EE];
__device__ int     g_bsum[64];
__device__ float   g_pool[BB * 64];
__device__ int     g_start[BB];
__device__ int     g_end[BB];

// ---------------- f32x2 helpers ----------------
typedef unsigned long long u64;
__device__ __forceinline__ u64 splat2(float x) {
    u64 r; asm("mov.b64 %0,{%1,%1};" : "=l"(r) : "f"(x)); return r;
}
__device__ __forceinline__ u64 fma2(u64 a, u64 b, u64 c) {
    u64 d; asm("fma.rn.f32x2 %0,%1,%2,%3;" : "=l"(d) : "l"(a), "l"(b), "l"(c)); return d;
}
__device__ __forceinline__ u64 add2(u64 a, u64 b) {
    u64 d; asm("add.rn.f32x2 %0,%1,%2;" : "=l"(d) : "l"(a), "l"(b)); return d;
}
__device__ __forceinline__ float2 unpk(u64 v) {
    float2 f; asm("mov.b64 {%0,%1},%2;" : "=f"(f.x), "=f"(f.y) : "l"(v)); return f;
}
__device__ __forceinline__ u64 pk2(float x, float y) {
    u64 r; asm("mov.b64 %0,{%1,%2};" : "=l"(r) : "f"(x), "f"(y)); return r;
}
__device__ __forceinline__ float2 f2add(float2 a, float2 b) {
    a.x += b.x; a.y += b.y; return a;
}

// ---------------- launch 1: init + h0(fp16) + degree histogram ----------------
__global__ void fused_init(const float* __restrict__ x, const float* __restrict__ pos,
                           const int* __restrict__ batch, const int* __restrict__ dst) {
    int i = blockIdx.x * blockDim.x + threadIdx.x;
    if (i < NN * 32) {
        int v = i >> 5, c = i & 31;
        float val = (c < 29) ? x[v * 29 + c] : pos[v * 3 + (c - 29)];
        g_h0h[i] = __float2half_rn(val);
    }
    if (i < EE) {
        g_rank[i] = atomicAdd(&g_cursor[dst[i]], 1);
    }
    if (i < NN) {
        int bi = __ldg(&batch[i]);
        if (i == 0 || __ldg(&batch[i - 1]) != bi) g_start[bi] = i;
        if (i == NN - 1 || __ldg(&batch[i + 1]) != bi) g_end[bi] = i + 1;
    }
    if (i == 0) g_rowptr[0] = 0;
    if (i < BB * 64) g_pool[i] = 0.f;
}

// ---------------- launch 2: per-block scan of degrees ----------------
__global__ void scanA_kernel() {
    __shared__ int wsum[32];
    int i = blockIdx.x * 1024 + threadIdx.x;
    int lane = threadIdx.x & 31, wid = threadIdx.x >> 5;
    int xx = (i < NN) ? g_cursor[i] : 0;
    #pragma unroll
    for (int o = 1; o < 32; o <<= 1) {
        int y = __shfl_up_sync(0xffffffffu, xx, o);
        if (lane >= o) xx += y;
    }
    if (lane == 31) wsum[wid] = xx;
    __syncthreads();
    if (wid == 0) {
        int s = wsum[lane];
        #pragma unroll
        for (int o = 1; o < 32; o <<= 1) {
            int y = __shfl_up_sync(0xffffffffu, s, o);
            if (lane >= o) s += y;
        }
        wsum[lane] = s;
    }
    __syncthreads();
    int incl = xx + (wid ? wsum[wid - 1] : 0);
    if (i < NN) g_rowptr[i + 1] = incl;
    if (threadIdx.x == 1023) g_bsum[blockIdx.x] = incl;
}

// ---------------- launch 3: scatter + rowptr finalize + cursor re-zero ----------------
__global__ void scatter_fix(const int* __restrict__ src, const int* __restrict__ dst) {
    __shared__ int sb[NSCAN_BLK + 1];
    if (threadIdx.x < NSCAN_BLK) sb[threadIdx.x + 1] = g_bsum[threadIdx.x];
    __syncthreads();
    if (threadIdx.x == 0) {
        int run = 0;
        #pragma unroll
        for (int k = 0; k < NSCAN_BLK; k++) { int t = sb[k + 1]; sb[k] = run; run += t; }
    }
    __syncthreads();

    int e = blockIdx.x * blockDim.x + threadIdx.x;
    if (e <= NN) {
        int add = (e > 0) ? sb[(e - 1) >> 10] : 0;
        g_rowptr2[e] = g_rowptr[e] + add;
    }
    if (e < EE) {
        int d = dst[e];
        int base = g_rowptr[d] + ((d > 0) ? sb[(d - 1) >> 10] : 0);
        g_csr[base + g_rank[e]] = src[e];
    }
    if (e < NN) g_cursor[e] = 0;
}

// ---------------- gather kernel (per layer): z = h[v] + sum h[src] ----------------
// Dedicated latency machine: 8 warps/block, 4 nodes/warp, span cache in SMEM,
// 16 loads in flight. No weights, no block syncs -> high occupancy.
template <int C>
__global__ void __launch_bounds__(256, 8) gather_kernel(const void* __restrict__ h_in_v) {
    __shared__ int sidx_all[8][256];
    int* sidx = sidx_all[threadIdx.x >> 5];

    const int lane  = threadIdx.x & 31;
    const int vbase = (blockIdx.x * 8 + (threadIdx.x >> 5)) * 4;

    int rp[5];
    #pragma unroll
    for (int k = 0; k < 5; k++) {
        int v = vbase + k; if (v > NN) v = NN;
        rp[k] = __ldg(&g_rowptr2[v]);
    }
    const int e0 = rp[0];
    const int span = rp[4] - e0;
    const int cap = (span < 256) ? span : 256;

    for (int k = lane; k < cap; k += 32) sidx[k] = __ldg(&g_csr[e0 + k]);
    __syncwarp();

    if (C == 64) {
        const __half2* hp = (const __half2*)h_in_v;
        #pragma unroll
        for (int n = 0; n < 4; n++) {
            int v = vbase + n;
            if (v >= NN) break;
            float2 z = __half22float2(__ldg(hp + (size_t)v * 32 + lane));
            int b0 = rp[n] - e0, b1e = rp[n + 1] - e0;
            if (b1e <= cap) {
                int k = b0;
                for (; k + 16 <= b1e; k += 16) {
                    float2 a[16];
                    #pragma unroll
                    for (int j = 0; j < 16; j++)
                        a[j] = __half22float2(__ldg(hp + (size_t)sidx[k + j] * 32 + lane));
                    float2 s0 = f2add(f2add(a[0], a[1]),   f2add(a[2], a[3]));
                    float2 s1 = f2add(f2add(a[4], a[5]),   f2add(a[6], a[7]));
                    float2 s2 = f2add(f2add(a[8], a[9]),   f2add(a[10], a[11]));
                    float2 s3 = f2add(f2add(a[12], a[13]), f2add(a[14], a[15]));
                    z = f2add(z, f2add(f2add(s0, s1), f2add(s2, s3)));
                }
                for (; k + 4 <= b1e; k += 4) {
                    float2 a0 = __half22float2(__ldg(hp + (size_t)sidx[k] * 32 + lane));
                    float2 a1 = __half22float2(__ldg(hp + (size_t)sidx[k + 1] * 32 + lane));
                    float2 a2 = __half22float2(__ldg(hp + (size_t)sidx[k + 2] * 32 + lane));
                    float2 a3 = __half22float2(__ldg(hp + (size_t)sidx[k + 3] * 32 + lane));
                    z = f2add(z, f2add(f2add(a0, a1), f2add(a2, a3)));
                }
                for (; k < b1e; k++)
                    z = f2add(z, __half22float2(__ldg(hp + (size_t)sidx[k] * 32 + lane)));
            } else {
                for (int k = b0; k < b1e; k++) {
                    int s = __ldg(&g_csr[e0 + k]);
                    z = f2add(z, __half22float2(__ldg(hp + (size_t)s * 32 + lane)));
                }
            }
            ((__half2*)g_z)[(size_t)v * 32 + lane] = __float22half2_rn(z);
        }
    } else {
        const __half* hf = (const __half*)h_in_v;   // lane owns feature l (C=32)
        #pragma unroll
        for (int n = 0; n < 4; n++) {
            int v = vbase + n;
            if (v >= NN) break;
            float z = __half2float(__ldg(hf + (size_t)v * 32 + lane));
            int b0 = rp[n] - e0, b1e = rp[n + 1] - e0;
            if (b1e <= cap) {
                int k = b0;
                for (; k + 16 <= b1e; k += 16) {
                    float a[16];
                    #pragma unroll
                    for (int j = 0; j < 16; j++)
                        a[j] = __half2float(__ldg(hf + (size_t)sidx[k + j] * 32 + lane));
                    float s0 = (a[0] + a[1]) + (a[2] + a[3]);
                    float s1 = (a[4] + a[5]) + (a[6] + a[7]);
                    float s2 = (a[8] + a[9]) + (a[10] + a[11]);
                    float s3 = (a[12] + a[13]) + (a[14] + a[15]);
                    z += (s0 + s1) + (s2 + s3);
                }
                for (; k < b1e; k++)
                    z += __half2float(__ldg(hf + (size_t)sidx[k] * 32 + lane));
            } else {
                for (int k = b0; k < b1e; k++)
                    z += __half2float(__ldg(hf + (size_t)__ldg(&g_csr[e0 + k]) * 32 + lane));
            }
            g_z[(size_t)v * 64 + lane] = __float2half_rn(z);
        }
    }
}

// ---------------- MLP kernel (per layer): h_out = (relu(z@W1+b1))@W2+b2 ----------------
// 8 warps/block, 8 nodes/warp (halved weight-LDS per MAC). z staged fp32 in a
// per-warp tile; w0..w3 hoisted per c4; 8 independent f32x2 acc chains.
template <int C, bool RELU_OUT, bool POOL>
__global__ void __launch_bounds__(256) mlp_kernel(
    __half2* __restrict__ h_out,
    const float* __restrict__ W1, const float* __restrict__ b1,
    const float* __restrict__ W2, const float* __restrict__ b2,
    const int* __restrict__ batch, float bias_scale, float store_scale)
{
    extern __shared__ float smem[];
    float* sW1 = smem;                   // C*64
    float* sW2 = sW1 + C * 64;           // 64*64
    float* sb1 = sW2 + 4096;             // 64
    float* sb2 = sb1 + 64;               // 64
    float* ztile = sb2 + 64 + (threadIdx.x >> 5) * 512;   // 8 nodes x 64

    for (int i = threadIdx.x; i < C * 64; i += 256) sW1[i] = W1[i];
    for (int i = threadIdx.x; i < 64 * 64; i += 256) sW2[i] = W2[i];
    if (threadIdx.x < 64) {
        sb1[threadIdx.x] = b1[threadIdx.x] * bias_scale;
        sb2[threadIdx.x] = b2[threadIdx.x] * bias_scale;
    }
    __syncthreads();

    const int lane  = threadIdx.x & 31;
    const int vbase = (blockIdx.x * 8 + (threadIdx.x >> 5)) * 8;

    // ---- stage z (fp16 gmem -> fp32 tile) ----
    #pragma unroll
    for (int n = 0; n < 8; n++) {
        int v = vbase + n;
        if (C == 64) {
            float2 f = (v < NN) ? __half22float2(__ldg((const __half2*)g_z + (size_t)v * 32 + lane))
                                : make_float2(0.f, 0.f);
            ((u64*)(ztile + n * 64))[lane] = pk2(f.x, f.y);
        } else {
            float f = (v < NN) ? __half2float(__ldg(g_z + (size_t)v * 64 + lane)) : 0.f;
            ztile[n * 64 + lane] = f;   // row stride 64, first 32 used
        }
    }
    __syncwarp();

    const int ZS = 64;

    // ---- GEMV1: t = relu(z @ W1 + b1s) ----
    u64 acc[8];
    {
        u64 bias = ((const u64*)sb1)[lane];
        #pragma unroll
        for (int n = 0; n < 8; n++) acc[n] = bias;
    }
    for (int c4 = 0; c4 < C; c4 += 4) {
        u64 w0 = ((const u64*)(sW1 + (c4 + 0) * 64))[lane];
        u64 w1 = ((const u64*)(sW1 + (c4 + 1) * 64))[lane];
        u64 w2 = ((const u64*)(sW1 + (c4 + 2) * 64))[lane];
        u64 w3 = ((const u64*)(sW1 + (c4 + 3) * 64))[lane];
        #pragma unroll
        for (int n = 0; n < 8; n++) {
            float4 zq = *(const float4*)&ztile[n * ZS + c4];
            acc[n] = fma2(splat2(zq.x), w0, acc[n]);
            acc[n] = fma2(splat2(zq.y), w1, acc[n]);
            acc[n] = fma2(splat2(zq.z), w2, acc[n]);
            acc[n] = fma2(splat2(zq.w), w3, acc[n]);
        }
    }
    __syncwarp();
    #pragma unroll
    for (int n = 0; n < 8; n++) {
        float2 f = unpk(acc[n]);
        ((u64*)(ztile + n * 64))[lane] = pk2(fmaxf(f.x, 0.f), fmaxf(f.y, 0.f));
    }
    __syncwarp();

    // ---- GEMV2: o = t @ W2 + b2s ----
    {
        u64 bias = ((const u64*)sb2)[lane];
        #pragma unroll
        for (int n = 0; n < 8; n++) acc[n] = bias;
    }
    for (int c4 = 0; c4 < 64; c4 += 4) {
        u64 w0 = ((const u64*)(sW2 + (c4 + 0) * 64))[lane];
        u64 w1 = ((const u64*)(sW2 + (c4 + 1) * 64))[lane];
        u64 w2 = ((const u64*)(sW2 + (c4 + 2) * 64))[lane];
        u64 w3 = ((const u64*)(sW2 + (c4 + 3) * 64))[lane];
        #pragma unroll
        for (int n = 0; n < 8; n++) {
            float4 zq = *(const float4*)&ztile[n * 64 + c4];
            acc[n] = fma2(splat2(zq.x), w0, acc[n]);
            acc[n] = fma2(splat2(zq.y), w1, acc[n]);
            acc[n] = fma2(splat2(zq.z), w2, acc[n]);
            acc[n] = fma2(splat2(zq.w), w3, acc[n]);
        }
    }

    if (POOL) {
        if (vbase + 7 < NN) {
            int ga = __ldg(&batch[vbase]);
            int gb = __ldg(&batch[vbase + 7]);
            if (ga == gb) {
                u64 s = add2(add2(add2(acc[0], acc[1]), add2(acc[2], acc[3])),
                             add2(add2(acc[4], acc[5]), add2(acc[6], acc[7])));
                float2 f = unpk(s);
                atomicAdd((float2*)&g_pool[ga * 64 + 2 * lane], f);
                return;
            }
        }
        #pragma unroll
        for (int n = 0; n < 8; n++) {
            int v = vbase + n;
            if (v >= NN) break;
            int g = __ldg(&batch[v]);
            float2 f = unpk(acc[n]);
            atomicAdd((float2*)&g_pool[g * 64 + 2 * lane], f);
        }
    } else {
        #pragma unroll
        for (int n = 0; n < 8; n++) {
            int v = vbase + n;
            if (v >= NN) break;
            float2 f = unpk(acc[n]);
            if (RELU_OUT) { f.x = fmaxf(f.x, 0.f); f.y = fmaxf(f.y, 0.f); }
            f.x *= store_scale; f.y *= store_scale;
            h_out[(size_t)v * 32 + lane] = __float22half2_rn(f);
        }
    }
}

// ---------------- final linear ----------------
// pooled sums carry scale 4^-(LL-1); multiply back by 4^6 = 4096.
__global__ void final_kernel(const float* __restrict__ lin_w,
                             const float* __restrict__ lin_b,
                             float* __restrict__ out) {
    int gtid = blockIdx.x * blockDim.x + threadIdx.x;
    int g = gtid >> 5, lane = threadIdx.x & 31;
    if (g >= BB) return;
    float s = g_pool[g * 64 + lane] * __ldg(&lin_w[lane]) +
              g_pool[g * 64 + 32 + lane] * __ldg(&lin_w[32 + lane]);
    #pragma unroll
    for (int o = 16; o; o >>= 1) s += __shfl_xor_sync(0xffffffffu, s, o);
    if (lane == 0) {
        float cnt = (float)(g_end[g] - g_start[g]);
        out[g] = (s * 4096.0f) / fmaxf(cnt, 1.f) + lin_b[0];
    }
}

// ---------------- launch ----------------
extern "C" void kernel_launch(void* const* d_in, const int* in_sizes, int n_in,
                              void* d_out, int out_size) {
    const float* x     = (const float*)d_in[0];
    const float* pos   = (const float*)d_in[1];
    const int*   ei    = (const int*)d_in[2];
    const int*   batch = (const int*)d_in[3];
    const float* W1f   = (const float*)d_in[4];
    const float* W1r   = (const float*)d_in[5];
    const float* b1    = (const float*)d_in[6];
    const float* W2    = (const float*)d_in[7];
    const float* b2    = (const float*)d_in[8];
    const float* lin_w = (const float*)d_in[9];
    const float* lin_b = (const float*)d_in[10];
    float* out = (float*)d_out;

    const int* src = ei;
    const int* dst = ei + EE;

    void *h0h, *hA, *hB;
    cudaGetSymbolAddress(&h0h, g_h0h);
    cudaGetSymbolAddress(&hA, g_hA);
    cudaGetSymbolAddress(&hB, g_hB);

    // mlp smem (floats): W1 + W2 + 128 bias + 8 warps * 512 tile
    const int smem32 = (32 * 64 + 4096 + 128 + 8 * 512) * 4;
    const int smem64 = (64 * 64 + 4096 + 128 + 8 * 512) * 4;
    cudaFuncSetAttribute((const void*)mlp_kernel<32, true,  false>, cudaFuncAttributeMaxDynamicSharedMemorySize, smem32);
    cudaFuncSetAttribute((const void*)mlp_kernel<64, true,  false>, cudaFuncAttributeMaxDynamicSharedMemorySize, smem64);
    cudaFuncSetAttribute((const void*)mlp_kernel<64, false, true>,  cudaFuncAttributeMaxDynamicSharedMemorySize, smem64);

    // prologue (3 launches)
    fused_init<<<(NN * 32 + 255) / 256, 256>>>(x, pos, batch, dst);
    scanA_kernel<<<NSCAN_BLK, 1024>>>();
    scatter_fix<<<(EE + 255) / 256, 256>>>(src, dst);

    const int GB = (NN + 31) / 32;   // gather: 32 nodes/block
    const int MB = (NN + 63) / 64;   // mlp: 64 nodes/block (8 warps x 8)

    // layer 0 (C=32): bias_scale 1, store scale 1/4
    gather_kernel<32><<<GB, 256>>>(h0h);
    mlp_kernel<32, true, false><<<MB, 256, smem32>>>((__half2*)hA, W1f, b1, W2, b2,
                                                     batch, 1.0f, 0.25f);

    void* cur = hA;
    void* nxt = hB;
    float bs = 0.25f;   // input scale of layer l is 4^-l
    for (int l = 1; l < LL; l++) {
        const float* w1 = W1r + (size_t)(l - 1) * HH * HH;
        gather_kernel<64><<<GB, 256>>>(cur);
        if (l < LL - 1) {
            mlp_kernel<64, true, false><<<MB, 256, smem64>>>((__half2*)nxt, w1, b1 + l * HH,
                                                             W2 + (size_t)l * HH * HH, b2 + l * HH,
                                                             batch, bs, 0.25f);
            void* t = cur; cur = nxt; nxt = t;
        } else {
            mlp_kernel<64, false, true><<<MB, 256, smem64>>>((__half2*)nxt, w1, b1 + l * HH,
                                                             W2 + (size_t)l * HH * HH, b2 + l * HH,
                                                             batch, bs, 1.0f);
        }
        bs *= 0.25f;
    }

    final_kernel<<<(BB * 32 + 255) / 256, 256>>>(lin_w, lin_b, out);
}

// round 11
// speedup vs baseline: 1.2945x; 1.2945x over previous
#include <cuda_runtime.h>
#include <cuda_bf16.h>
#include <cstdint>

#define NN 50000
#define EE 800000
#define BB 50
#define LL 7
#define NSCAN_BLK 49

// ---------------- scratch (device globals; no allocations) ----------------
// g_cursor must be zero at entry each call (re-zeroed by scatter_fix).
__device__ __nv_bfloat16  g_h0h[NN * 32];   // layer-0 h (bf16)
__device__ __nv_bfloat162 g_hA[NN * 32];    // hidden ping
__device__ __nv_bfloat162 g_hB[NN * 32];    // hidden pong
__device__ __nv_bfloat16  g_z[NN * 64];     // aggregated z (row stride 64)
__device__ float          g_hF[NN * 64];    // final-layer h (fp32)
__device__ int   g_rowptr[NN + 1];
__device__ int   g_rowptr2[NN + 1];
__device__ int   g_cursor[NN];
__device__ int   g_rank[EE];
__device__ int   g_csr[EE];
__device__ int   g_bsum[64];
__device__ float g_pool[BB * 64];
__device__ int   g_start[BB];
__device__ int   g_end[BB];

__device__ __forceinline__ uint32_t smem_to_u32(const void* p) {
    uint32_t a;
    asm("{ .reg .u64 t; cvta.to.shared.u64 t, %1; cvt.u32.u64 %0, t; }" : "=r"(a) : "l"(p));
    return a;
}
__device__ __forceinline__ float2 f2add(float2 a, float2 b) { a.x += b.x; a.y += b.y; return a; }

// ---------------- mma.sync helpers (baseline sm_80 PTX; works on sm_103) ----------------
__device__ __forceinline__ void ldsm_x4(uint32_t r[4], uint32_t addr) {
    asm volatile("ldmatrix.sync.aligned.m8n8.x4.shared.b16 {%0,%1,%2,%3}, [%4];"
        : "=r"(r[0]), "=r"(r[1]), "=r"(r[2]), "=r"(r[3]) : "r"(addr));
}
__device__ __forceinline__ void ldsm_x2(uint32_t r[2], uint32_t addr) {
    asm volatile("ldmatrix.sync.aligned.m8n8.x2.shared.b16 {%0,%1}, [%2];"
        : "=r"(r[0]), "=r"(r[1]) : "r"(addr));
}
__device__ __forceinline__ void mma16816(float d[4], const uint32_t a[4], const uint32_t b[2]) {
    asm volatile(
        "mma.sync.aligned.m16n8k16.row.col.f32.bf16.bf16.f32 "
        "{%0,%1,%2,%3}, {%4,%5,%6,%7}, {%8,%9}, {%0,%1,%2,%3};"
        : "+f"(d[0]), "+f"(d[1]), "+f"(d[2]), "+f"(d[3])
        : "r"(a[0]), "r"(a[1]), "r"(a[2]), "r"(a[3]), "r"(b[0]), "r"(b[1]));
}

// ---------------- launch 1: init + h0(bf16) + degree histogram ----------------
__global__ void fused_init(const float* __restrict__ x, const float* __restrict__ pos,
                           const int* __restrict__ batch, const int* __restrict__ dst) {
    int i = blockIdx.x * blockDim.x + threadIdx.x;
    if (i < NN * 32) {
        int v = i >> 5, c = i & 31;
        float val = (c < 29) ? x[v * 29 + c] : pos[v * 3 + (c - 29)];
        g_h0h[i] = __float2bfloat16_rn(val);
    }
    if (i < EE) g_rank[i] = atomicAdd(&g_cursor[dst[i]], 1);
    if (i < NN) {
        int bi = __ldg(&batch[i]);
        if (i == 0 || __ldg(&batch[i - 1]) != bi) g_start[bi] = i;
        if (i == NN - 1 || __ldg(&batch[i + 1]) != bi) g_end[bi] = i + 1;
    }
    if (i == 0) g_rowptr[0] = 0;
    if (i < BB * 64) g_pool[i] = 0.f;
}

// ---------------- launch 2: per-block scan of degrees ----------------
__global__ void scanA_kernel() {
    __shared__ int wsum[32];
    int i = blockIdx.x * 1024 + threadIdx.x;
    int lane = threadIdx.x & 31, wid = threadIdx.x >> 5;
    int xx = (i < NN) ? g_cursor[i] : 0;
    #pragma unroll
    for (int o = 1; o < 32; o <<= 1) {
        int y = __shfl_up_sync(0xffffffffu, xx, o);
        if (lane >= o) xx += y;
    }
    if (lane == 31) wsum[wid] = xx;
    __syncthreads();
    if (wid == 0) {
        int s = wsum[lane];
        #pragma unroll
        for (int o = 1; o < 32; o <<= 1) {
            int y = __shfl_up_sync(0xffffffffu, s, o);
            if (lane >= o) s += y;
        }
        wsum[lane] = s;
    }
    __syncthreads();
    int incl = xx + (wid ? wsum[wid - 1] : 0);
    if (i < NN) g_rowptr[i + 1] = incl;
    if (threadIdx.x == 1023) g_bsum[blockIdx.x] = incl;
}

// ---------------- launch 3: scatter + rowptr finalize + cursor re-zero ----------------
__global__ void scatter_fix(const int* __restrict__ src, const int* __restrict__ dst) {
    __shared__ int sb[NSCAN_BLK + 1];
    if (threadIdx.x < NSCAN_BLK) sb[threadIdx.x + 1] = g_bsum[threadIdx.x];
    __syncthreads();
    if (threadIdx.x == 0) {
        int run = 0;
        #pragma unroll
        for (int k = 0; k < NSCAN_BLK; k++) { int t = sb[k + 1]; sb[k] = run; run += t; }
    }
    __syncthreads();
    int e = blockIdx.x * blockDim.x + threadIdx.x;
    if (e <= NN) {
        int add = (e > 0) ? sb[(e - 1) >> 10] : 0;
        g_rowptr2[e] = g_rowptr[e] + add;
    }
    if (e < EE) {
        int d = dst[e];
        int base = g_rowptr[d] + ((d > 0) ? sb[(d - 1) >> 10] : 0);
        g_csr[base + g_rank[e]] = src[e];
    }
    if (e < NN) g_cursor[e] = 0;
}

// ---------------- gather kernel: z = h[v] + sum h[src] (bf16) ----------------
template <int C>
__global__ void __launch_bounds__(256, 8) gather_kernel(const void* __restrict__ h_in_v) {
    __shared__ int sidx_all[8][256];
    int* sidx = sidx_all[threadIdx.x >> 5];
    const int lane  = threadIdx.x & 31;
    const int vbase = (blockIdx.x * 8 + (threadIdx.x >> 5)) * 4;

    int rp[5];
    #pragma unroll
    for (int k = 0; k < 5; k++) {
        int v = vbase + k; if (v > NN) v = NN;
        rp[k] = __ldg(&g_rowptr2[v]);
    }
    const int e0 = rp[0];
    const int span = rp[4] - e0;
    const int cap = (span < 256) ? span : 256;
    for (int k = lane; k < cap; k += 32) sidx[k] = __ldg(&g_csr[e0 + k]);
    __syncwarp();

    if (C == 64) {
        const __nv_bfloat162* hp = (const __nv_bfloat162*)h_in_v;
        #pragma unroll
        for (int n = 0; n < 4; n++) {
            int v = vbase + n;
            if (v >= NN) break;
            float2 z = __bfloat1622float2(__ldg(hp + (size_t)v * 32 + lane));
            int b0 = rp[n] - e0, b1e = rp[n + 1] - e0;
            if (b1e <= cap) {
                int k = b0;
                for (; k + 16 <= b1e; k += 16) {
                    float2 a[16];
                    #pragma unroll
                    for (int j = 0; j < 16; j++)
                        a[j] = __bfloat1622float2(__ldg(hp + (size_t)sidx[k + j] * 32 + lane));
                    float2 s0 = f2add(f2add(a[0], a[1]),   f2add(a[2], a[3]));
                    float2 s1 = f2add(f2add(a[4], a[5]),   f2add(a[6], a[7]));
                    float2 s2 = f2add(f2add(a[8], a[9]),   f2add(a[10], a[11]));
                    float2 s3 = f2add(f2add(a[12], a[13]), f2add(a[14], a[15]));
                    z = f2add(z, f2add(f2add(s0, s1), f2add(s2, s3)));
                }
                for (; k + 4 <= b1e; k += 4) {
                    float2 a0 = __bfloat1622float2(__ldg(hp + (size_t)sidx[k] * 32 + lane));
                    float2 a1 = __bfloat1622float2(__ldg(hp + (size_t)sidx[k + 1] * 32 + lane));
                    float2 a2 = __bfloat1622float2(__ldg(hp + (size_t)sidx[k + 2] * 32 + lane));
                    float2 a3 = __bfloat1622float2(__ldg(hp + (size_t)sidx[k + 3] * 32 + lane));
                    z = f2add(z, f2add(f2add(a0, a1), f2add(a2, a3)));
                }
                for (; k < b1e; k++)
                    z = f2add(z, __bfloat1622float2(__ldg(hp + (size_t)sidx[k] * 32 + lane)));
            } else {
                for (int k = b0; k < b1e; k++) {
                    int s = __ldg(&g_csr[e0 + k]);
                    z = f2add(z, __bfloat1622float2(__ldg(hp + (size_t)s * 32 + lane)));
                }
            }
            ((__nv_bfloat162*)g_z)[(size_t)v * 32 + lane] = __float22bfloat162_rn(z);
        }
    } else {
        const __nv_bfloat16* hf = (const __nv_bfloat16*)h_in_v;
        #pragma unroll
        for (int n = 0; n < 4; n++) {
            int v = vbase + n;
            if (v >= NN) break;
            float z = __bfloat162float(__ldg(hf + (size_t)v * 32 + lane));
            int b0 = rp[n] - e0, b1e = rp[n + 1] - e0;
            if (b1e <= cap) {
                int k = b0;
                for (; k + 16 <= b1e; k += 16) {
                    float a[16];
                    #pragma unroll
                    for (int j = 0; j < 16; j++)
                        a[j] = __bfloat162float(__ldg(hf + (size_t)sidx[k + j] * 32 + lane));
                    float s0 = (a[0] + a[1]) + (a[2] + a[3]);
                    float s1 = (a[4] + a[5]) + (a[6] + a[7]);
                    float s2 = (a[8] + a[9]) + (a[10] + a[11]);
                    float s3 = (a[12] + a[13]) + (a[14] + a[15]);
                    z += (s0 + s1) + (s2 + s3);
                }
                for (; k < b1e; k++)
                    z += __bfloat162float(__ldg(hf + (size_t)sidx[k] * 32 + lane));
            } else {
                for (int k = b0; k < b1e; k++)
                    z += __bfloat162float(__ldg(hf + (size_t)__ldg(&g_csr[e0 + k]) * 32 + lane));
            }
            g_z[(size_t)v * 64 + lane] = __float2bfloat16_rn(z);
        }
    }
}

// ---------------- MLP via mma.sync (one CTA = 128 nodes, 8 warps x 16) ----------------
// SMEM byte offsets; all matrix tiles use 144B row stride (conflict-free ldmatrix)
#define OFF_ZT   0
#define OFF_W1HI 18432
#define OFF_W1LO 27648
#define OFF_W2HI 36864
#define OFF_W2LO 46080
#define OFF_B1   55296
#define OFF_B2   55552
#define MLP_SMEM 55808

// one warp: A = tile rows [16][K] bf16 (stride 144B); B = transposed weights [64][K]
template <int KCH>
__device__ __forceinline__ void gemv16(uint32_t a_base, uint32_t whi, uint32_t wlo,
                                       float acc[8][4], int lane) {
    uint32_t a[KCH][4];
    uint32_t arow = a_base + (lane & 15) * 144 + ((lane >> 4) << 4);
    #pragma unroll
    for (int kc = 0; kc < KCH; kc++) ldsm_x4(a[kc], arow + kc * 32);
    uint32_t bro = (lane & 7) * 144 + ((lane & 8) ? 16 : 0);
    #pragma unroll
    for (int nc = 0; nc < 8; nc++) {
        #pragma unroll
        for (int i = 0; i < 4; i++) acc[nc][i] = 0.f;
        #pragma unroll
        for (int kc = 0; kc < KCH; kc++) {
            uint32_t bh[2], bl[2];
            ldsm_x2(bh, whi + bro + nc * 1152 + kc * 32);
            mma16816(acc[nc], a[kc], bh);
            ldsm_x2(bl, wlo + bro + nc * 1152 + kc * 32);
            mma16816(acc[nc], a[kc], bl);
        }
    }
}

template <int C, bool RELU_OUT, bool LAST>
__global__ void __launch_bounds__(256) mlp_mma(
    const float* __restrict__ W1, const float* __restrict__ b1,
    const float* __restrict__ W2, const float* __restrict__ b2,
    __nv_bfloat162* __restrict__ h_out)
{
    extern __shared__ char smem[];
    const uint32_t sb = smem_to_u32(smem);
    const int tid = threadIdx.x, wid = tid >> 5, lane = tid & 31;
    const int vbase = blockIdx.x * 128;
    const int wrow = wid * 16;

    // stage split-bf16 transposed weights Wt[f][c], stride 144B
    for (int i = tid; i < C * 64; i += 256) {
        int c = i >> 6, f = i & 63;
        float w = __ldg(&W1[i]);
        __nv_bfloat16 hi = __float2bfloat16_rn(w);
        __nv_bfloat16 lo = __float2bfloat16_rn(w - __bfloat162float(hi));
        *(__nv_bfloat16*)(smem + OFF_W1HI + f * 144 + c * 2) = hi;
        *(__nv_bfloat16*)(smem + OFF_W1LO + f * 144 + c * 2) = lo;
    }
    for (int i = tid; i < 64 * 64; i += 256) {
        int c = i >> 6, f = i & 63;
        float w = __ldg(&W2[i]);
        __nv_bfloat16 hi = __float2bfloat16_rn(w);
        __nv_bfloat16 lo = __float2bfloat16_rn(w - __bfloat162float(hi));
        *(__nv_bfloat16*)(smem + OFF_W2HI + f * 144 + c * 2) = hi;
        *(__nv_bfloat16*)(smem + OFF_W2LO + f * 144 + c * 2) = lo;
    }
    if (tid < 64) {
        ((float*)(smem + OFF_B1))[tid] = __ldg(&b1[tid]);
        ((float*)(smem + OFF_B2))[tid] = __ldg(&b2[tid]);
    }

    // stage z rows (16B blocks; swizzle-free padded layout)
    constexpr int BPR = C / 8;
    for (int i = tid; i < 128 * BPR; i += 256) {
        int row = i / BPR, j = i % BPR;
        int v = vbase + row;
        if (v < NN) {
            uint4 val = __ldg((const uint4*)g_z + (size_t)v * 8 + j);
            *(uint4*)(smem + OFF_ZT + row * 144 + j * 16) = val;
        }
    }
    __syncthreads();

    float acc[8][4];
    const uint32_t abase = sb + OFF_ZT + wrow * 144;

    // ---- GEMV1: t = relu(z @ W1 + b1) ----
    gemv16<C / 16>(abase, sb + OFF_W1HI, sb + OFF_W1LO, acc, lane);
    {
        const float* b1s = (const float*)(smem + OFF_B1);
        int r0off = (wrow + (lane >> 2)) * 144;
        int cb = 2 * (lane & 3);
        #pragma unroll
        for (int nc = 0; nc < 8; nc++) {
            int n0 = nc * 8 + cb;
            float bx = b1s[n0], by = b1s[n0 + 1];
            __nv_bfloat162 p0 = __float22bfloat162_rn(
                make_float2(fmaxf(acc[nc][0] + bx, 0.f), fmaxf(acc[nc][1] + by, 0.f)));
            __nv_bfloat162 p1 = __float22bfloat162_rn(
                make_float2(fmaxf(acc[nc][2] + bx, 0.f), fmaxf(acc[nc][3] + by, 0.f)));
            *(uint32_t*)(smem + OFF_ZT + r0off + n0 * 2) = *(uint32_t*)&p0;
            *(uint32_t*)(smem + OFF_ZT + r0off + 8 * 144 + n0 * 2) = *(uint32_t*)&p1;
        }
    }
    __syncwarp();   // t tile rows are warp-private

    // ---- GEMV2: o = t @ W2 + b2 ----
    gemv16<4>(abase, sb + OFF_W2HI, sb + OFF_W2LO, acc, lane);
    {
        const float* b2s = (const float*)(smem + OFF_B2);
        int r0 = wrow + (lane >> 2);
        int v0 = vbase + r0, v1 = v0 + 8;
        int cb = 2 * (lane & 3);
        #pragma unroll
        for (int nc = 0; nc < 8; nc++) {
            int n0 = nc * 8 + cb;
            float bx = b2s[n0], by = b2s[n0 + 1];
            float x0 = acc[nc][0] + bx, y0 = acc[nc][1] + by;
            float x1 = acc[nc][2] + bx, y1 = acc[nc][3] + by;
            if (LAST) {
                if (v0 < NN) *(float2*)(g_hF + (size_t)v0 * 64 + n0) = make_float2(x0, y0);
                if (v1 < NN) *(float2*)(g_hF + (size_t)v1 * 64 + n0) = make_float2(x1, y1);
            } else {
                if (RELU_OUT) {
                    x0 = fmaxf(x0, 0.f); y0 = fmaxf(y0, 0.f);
                    x1 = fmaxf(x1, 0.f); y1 = fmaxf(y1, 0.f);
                }
                __nv_bfloat162 p0 = __float22bfloat162_rn(make_float2(x0, y0));
                __nv_bfloat162 p1 = __float22bfloat162_rn(make_float2(x1, y1));
                if (v0 < NN) *((uint32_t*)h_out + (size_t)v0 * 32 + (n0 >> 1)) = *(uint32_t*)&p0;
                if (v1 < NN) *((uint32_t*)h_out + (size_t)v1 * 32 + (n0 >> 1)) = *(uint32_t*)&p1;
            }
        }
    }
}

// ---------------- pooling + final linear ----------------
__global__ void pool_kernel(const int* __restrict__ batch) {
    int w = (blockIdx.x * 256 + threadIdx.x) >> 5;
    int lane = threadIdx.x & 31;
    int v0 = w * 8;
    if (v0 >= NN) return;
    int vend = v0 + 8; if (vend > NN) vend = NN;
    int g0 = __ldg(&batch[v0]);
    if (__ldg(&batch[vend - 1]) == g0) {
        float2 s = make_float2(0.f, 0.f);
        for (int v = v0; v < vend; v++)
            s = f2add(s, *(const float2*)(g_hF + (size_t)v * 64 + 2 * lane));
        atomicAdd((float2*)&g_pool[g0 * 64 + 2 * lane], s);
    } else {
        for (int v = v0; v < vend; v++) {
            int g = __ldg(&batch[v]);
            float2 f = *(const float2*)(g_hF + (size_t)v * 64 + 2 * lane);
            atomicAdd((float2*)&g_pool[g * 64 + 2 * lane], f);
        }
    }
}

__global__ void final_kernel(const float* __restrict__ lin_w,
                             const float* __restrict__ lin_b,
                             float* __restrict__ out) {
    int gtid = blockIdx.x * blockDim.x + threadIdx.x;
    int g = gtid >> 5, lane = threadIdx.x & 31;
    if (g >= BB) return;
    float s = g_pool[g * 64 + lane] * __ldg(&lin_w[lane]) +
              g_pool[g * 64 + 32 + lane] * __ldg(&lin_w[32 + lane]);
    #pragma unroll
    for (int o = 16; o; o >>= 1) s += __shfl_xor_sync(0xffffffffu, s, o);
    if (lane == 0) {
        float cnt = (float)(g_end[g] - g_start[g]);
        out[g] = s / fmaxf(cnt, 1.f) + lin_b[0];
    }
}

// ---------------- launch ----------------
extern "C" void kernel_launch(void* const* d_in, const int* in_sizes, int n_in,
                              void* d_out, int out_size) {
    const float* x     = (const float*)d_in[0];
    const float* pos   = (const float*)d_in[1];
    const int*   ei    = (const int*)d_in[2];
    const int*   batch = (const int*)d_in[3];
    const float* W1f   = (const float*)d_in[4];
    const float* W1r   = (const float*)d_in[5];
    const float* b1    = (const float*)d_in[6];
    const float* W2    = (const float*)d_in[7];
    const float* b2    = (const float*)d_in[8];
    const float* lin_w = (const float*)d_in[9];
    const float* lin_b = (const float*)d_in[10];
    float* out = (float*)d_out;

    const int* src = ei;
    const int* dst = ei + EE;

    void *h0h, *hA, *hB;
    cudaGetSymbolAddress(&h0h, g_h0h);
    cudaGetSymbolAddress(&hA, g_hA);
    cudaGetSymbolAddress(&hB, g_hB);

    cudaFuncSetAttribute((const void*)mlp_mma<32, true,  false>, cudaFuncAttributeMaxDynamicSharedMemorySize, MLP_SMEM);
    cudaFuncSetAttribute((const void*)mlp_mma<64, true,  false>, cudaFuncAttributeMaxDynamicSharedMemorySize, MLP_SMEM);
    cudaFuncSetAttribute((const void*)mlp_mma<64, false, true>,  cudaFuncAttributeMaxDynamicSharedMemorySize, MLP_SMEM);

    fused_init<<<(NN * 32 + 255) / 256, 256>>>(x, pos, batch, dst);
    scanA_kernel<<<NSCAN_BLK, 1024>>>();
    scatter_fix<<<(EE + 255) / 256, 256>>>(src, dst);

    const int GB = (NN + 31) / 32;      // gather blocks
    const int MB = (NN + 127) / 128;    // mma blocks (391)
    const int PB = ((NN / 8) * 32 + 255) / 256;   // pool: one warp per 8 nodes

    gather_kernel<32><<<GB, 256>>>(h0h);
    mlp_mma<32, true, false><<<MB, 256, MLP_SMEM>>>(W1f, b1, W2, b2, (__nv_bfloat162*)hA);

    void* cur = hA;
    void* nxt = hB;
    for (int l = 1; l < LL; l++) {
        const float* w1 = W1r + (size_t)(l - 1) * 64 * 64;
        gather_kernel<64><<<GB, 256>>>(cur);
        if (l < LL - 1) {
            mlp_mma<64, true, false><<<MB, 256, MLP_SMEM>>>(w1, b1 + l * 64,
                W2 + (size_t)l * 64 * 64, b2 + l * 64, (__nv_bfloat162*)nxt);
            void* t = cur; cur = nxt; nxt = t;
        } else {
            mlp_mma<64, false, true><<<MB, 256, MLP_SMEM>>>(w1, b1 + l * 64,
                W2 + (size_t)l * 64 * 64, b2 + l * 64, (__nv_bfloat162*)nxt);
        }
    }

    pool_kernel<<<PB, 256>>>(batch);
    final_kernel<<<(BB * 32 + 255) / 256, 256>>>(lin_w, lin_b, out);
}

// round 12
// speedup vs baseline: 1.4991x; 1.1580x over previous
#include <cuda_runtime.h>
#include <cuda_bf16.h>
#include <cstdint>

#define NN 50000
#define EE 800000
#define BB 50
#define LL 7
#define NSCAN_BLK 49

// ---------------- scratch (device globals; no allocations) ----------------
// g_cursor must be zero at entry each call (re-zeroed by scatter_fix).
__device__ __nv_bfloat16  g_h0h[NN * 32];   // layer-0 h (bf16, 64B rows)
__device__ __nv_bfloat162 g_hA[NN * 32];    // hidden ping (128B rows)
__device__ __nv_bfloat162 g_hB[NN * 32];    // hidden pong
__device__ __nv_bfloat16  g_z[NN * 64];     // aggregated z (128B rows)
__device__ float          g_hF[NN * 64];    // final-layer h (fp32)
__device__ __nv_bfloat16  g_Whi[LL * 2 * 4096];  // pre-split weights, transposed [f][c]
__device__ __nv_bfloat16  g_Wlo[LL * 2 * 4096];
__device__ int   g_rowptr[NN + 1];
__device__ int   g_rowptr2[NN + 1];
__device__ int   g_cursor[NN];
__device__ int   g_rank[EE];
__device__ int   g_csr[EE];
__device__ int   g_bsum[64];
__device__ float g_pool[BB * 64];
__device__ int   g_start[BB];
__device__ int   g_end[BB];

typedef unsigned long long u64;
__device__ __forceinline__ uint32_t smem_to_u32(const void* p) {
    uint32_t a;
    asm("{ .reg .u64 t; cvta.to.shared.u64 t, %1; cvt.u32.u64 %0, t; }" : "=r"(a) : "l"(p));
    return a;
}
__device__ __forceinline__ u64 add2(u64 a, u64 b) {
    u64 d; asm("add.rn.f32x2 %0,%1,%2;" : "=l"(d) : "l"(a), "l"(b)); return d;
}
__device__ __forceinline__ u64 bf2f2(uint32_t u) {   // bf16x2 -> packed f32x2 (exact)
    uint32_t lo = u << 16, hi = u & 0xFFFF0000u;
    u64 r; asm("mov.b64 %0,{%1,%2};" : "=l"(r) : "r"(lo), "r"(hi)); return r;
}
__device__ __forceinline__ float2 unpk(u64 v) {
    float2 f; asm("mov.b64 {%0,%1},%2;" : "=f"(f.x), "=f"(f.y) : "l"(v)); return f;
}
__device__ __forceinline__ u64 shfl_xor64(u64 v, int m) {
    uint32_t lo, hi;
    asm("mov.b64 {%0,%1},%2;" : "=r"(lo), "=r"(hi) : "l"(v));
    lo = __shfl_xor_sync(0xffffffffu, lo, m);
    hi = __shfl_xor_sync(0xffffffffu, hi, m);
    u64 r; asm("mov.b64 %0,{%1,%2};" : "=l"(r) : "r"(lo), "r"(hi)); return r;
}
__device__ __forceinline__ uint32_t pkbf(u64 acc) {   // packed f32x2 -> bf16x2
    float2 f = unpk(acc);
    __nv_bfloat162 b = __float22bfloat162_rn(f);
    return *(uint32_t*)&b;
}
__device__ __forceinline__ float2 f2add(float2 a, float2 b) { a.x += b.x; a.y += b.y; return a; }

// ---------------- mma.sync helpers ----------------
__device__ __forceinline__ void ldsm_x4(uint32_t r[4], uint32_t addr) {
    asm volatile("ldmatrix.sync.aligned.m8n8.x4.shared.b16 {%0,%1,%2,%3}, [%4];"
        : "=r"(r[0]), "=r"(r[1]), "=r"(r[2]), "=r"(r[3]) : "r"(addr));
}
__device__ __forceinline__ void ldsm_x2(uint32_t r[2], uint32_t addr) {
    asm volatile("ldmatrix.sync.aligned.m8n8.x2.shared.b16 {%0,%1}, [%2];"
        : "=r"(r[0]), "=r"(r[1]) : "r"(addr));
}
__device__ __forceinline__ void mma16816(float d[4], const uint32_t a[4], const uint32_t b[2]) {
    asm volatile(
        "mma.sync.aligned.m16n8k16.row.col.f32.bf16.bf16.f32 "
        "{%0,%1,%2,%3}, {%4,%5,%6,%7}, {%8,%9}, {%0,%1,%2,%3};"
        : "+f"(d[0]), "+f"(d[1]), "+f"(d[2]), "+f"(d[3])
        : "r"(a[0]), "r"(a[1]), "r"(a[2]), "r"(a[3]), "r"(b[0]), "r"(b[1]));
}

// ---------------- launch 1: init + h0 + histogram + weight pre-split ----------------
__global__ void fused_init(const float* __restrict__ x, const float* __restrict__ pos,
                           const int* __restrict__ batch, const int* __restrict__ dst,
                           const float* __restrict__ W1f, const float* __restrict__ W1r,
                           const float* __restrict__ W2) {
    int i = blockIdx.x * blockDim.x + threadIdx.x;
    if (i < NN * 32) {
        int v = i >> 5, c = i & 31;
        float val = (c < 29) ? x[v * 29 + c] : pos[v * 3 + (c - 29)];
        g_h0h[i] = __float2bfloat16_rn(val);
    }
    if (i < EE) g_rank[i] = atomicAdd(&g_cursor[dst[i]], 1);
    if (i < NN) {
        int bi = __ldg(&batch[i]);
        if (i == 0 || __ldg(&batch[i - 1]) != bi) g_start[bi] = i;
        if (i == NN - 1 || __ldg(&batch[i + 1]) != bi) g_end[bi] = i + 1;
    }
    if (i < 2 * LL * 4096) {   // weight pre-split, transposed [f][c]
        int l = i >> 13, m = (i >> 12) & 1, fc = i & 4095;
        int f = fc >> 6, c = fc & 63;
        float w = 0.f;
        if (m == 0) {
            if (l == 0) { if (c < 32) w = __ldg(&W1f[c * 64 + f]); }
            else w = __ldg(&W1r[(size_t)(l - 1) * 4096 + c * 64 + f]);
        } else {
            w = __ldg(&W2[(size_t)l * 4096 + c * 64 + f]);
        }
        __nv_bfloat16 hi = __float2bfloat16_rn(w);
        g_Whi[i] = hi;
        g_Wlo[i] = __float2bfloat16_rn(w - __bfloat162float(hi));
    }
    if (i == 0) g_rowptr[0] = 0;
    if (i < BB * 64) g_pool[i] = 0.f;
}

// ---------------- launch 2: per-block scan of degrees ----------------
__global__ void scanA_kernel() {
    __shared__ int wsum[32];
    int i = blockIdx.x * 1024 + threadIdx.x;
    int lane = threadIdx.x & 31, wid = threadIdx.x >> 5;
    int xx = (i < NN) ? g_cursor[i] : 0;
    #pragma unroll
    for (int o = 1; o < 32; o <<= 1) {
        int y = __shfl_up_sync(0xffffffffu, xx, o);
        if (lane >= o) xx += y;
    }
    if (lane == 31) wsum[wid] = xx;
    __syncthreads();
    if (wid == 0) {
        int s = wsum[lane];
        #pragma unroll
        for (int o = 1; o < 32; o <<= 1) {
            int y = __shfl_up_sync(0xffffffffu, s, o);
            if (lane >= o) s += y;
        }
        wsum[lane] = s;
    }
    __syncthreads();
    int incl = xx + (wid ? wsum[wid - 1] : 0);
    if (i < NN) g_rowptr[i + 1] = incl;
    if (threadIdx.x == 1023) g_bsum[blockIdx.x] = incl;
}

// ---------------- launch 3: scatter + rowptr finalize + cursor re-zero ----------------
__global__ void scatter_fix(const int* __restrict__ src, const int* __restrict__ dst) {
    __shared__ int sb[NSCAN_BLK + 1];
    if (threadIdx.x < NSCAN_BLK) sb[threadIdx.x + 1] = g_bsum[threadIdx.x];
    __syncthreads();
    if (threadIdx.x == 0) {
        int run = 0;
        #pragma unroll
        for (int k = 0; k < NSCAN_BLK; k++) { int t = sb[k + 1]; sb[k] = run; run += t; }
    }
    __syncthreads();
    int e = blockIdx.x * blockDim.x + threadIdx.x;
    if (e <= NN) {
        int add = (e > 0) ? sb[(e - 1) >> 10] : 0;
        g_rowptr2[e] = g_rowptr[e] + add;
    }
    if (e < EE) {
        int d = dst[e];
        int base = g_rowptr[d] + ((d > 0) ? sb[(d - 1) >> 10] : 0);
        g_csr[base + g_rank[e]] = src[e];
    }
    if (e < NN) g_cursor[e] = 0;
}

// ---------------- gather: 8 lanes per row, 4 rows concurrent per warp ----------------
// slot = lane>>3 picks the row (slot 0 batch 0 = self), q = lane&7 the 1/8 of the
// row. One LDG.128 (C=64) / LDG.64 (C=32) per lane per 4 rows -> 0.5 LSU ops/edge.
// Exact bf16->fp32 expansion (shl/and), packed f32x2 accumulate, xor-reduce(8,16).
template <int C>
__global__ void __launch_bounds__(256, 8) gather_kernel(const void* __restrict__ h_in_v) {
    __shared__ int sidx_all[8][260];
    int* sidx = sidx_all[threadIdx.x >> 5];
    const int lane = threadIdx.x & 31;
    const int slot = lane >> 3, q = lane & 7;
    const int vbase = (blockIdx.x * 8 + (threadIdx.x >> 5)) * 4;

    int rp[5];
    #pragma unroll
    for (int k = 0; k < 5; k++) {
        int v = vbase + k; if (v > NN) v = NN;
        rp[k] = __ldg(&g_rowptr2[v]);
    }
    const int e0 = rp[0];
    const int span = rp[4] - e0;
    const int cap = (span < 256) ? span : 256;
    for (int k = lane; k < cap; k += 32) sidx[k] = __ldg(&g_csr[e0 + k]);
    __syncwarp();

    #pragma unroll
    for (int n = 0; n < 4; n++) {
        int v = vbase + n;
        if (v >= NN) break;
        int b0 = rp[n] - e0;
        int deg = rp[n + 1] - rp[n];
        int total = deg + 1;

        if (C == 64) {
            const uint4* hp = (const uint4*)h_in_v;   // 8 uint4 per 128B row
            u64 a0 = 0, a1 = 0, a2 = 0, a3 = 0;
            if (rp[n + 1] - e0 <= cap) {
                #pragma unroll 2
                for (int base = 0; base < total; base += 4) {
                    int j = base + slot - 1;
                    int rk = b0 + j; rk = rk > 0 ? rk : 0;
                    int sv = sidx[rk];
                    int idx = (j < 0) ? v : sv;
                    if (j < deg) {
                        uint4 r = __ldg(hp + (size_t)idx * 8 + q);
                        a0 = add2(a0, bf2f2(r.x));
                        a1 = add2(a1, bf2f2(r.y));
                        a2 = add2(a2, bf2f2(r.z));
                        a3 = add2(a3, bf2f2(r.w));
                    }
                }
            } else {
                for (int base = 0; base < total; base += 4) {
                    int j = base + slot - 1;
                    if (j < deg) {
                        int idx = (j < 0) ? v : __ldg(&g_csr[rp[n] + j]);
                        uint4 r = __ldg(hp + (size_t)idx * 8 + q);
                        a0 = add2(a0, bf2f2(r.x));
                        a1 = add2(a1, bf2f2(r.y));
                        a2 = add2(a2, bf2f2(r.z));
                        a3 = add2(a3, bf2f2(r.w));
                    }
                }
            }
            #pragma unroll
            for (int m = 8; m <= 16; m <<= 1) {
                a0 = add2(a0, shfl_xor64(a0, m));
                a1 = add2(a1, shfl_xor64(a1, m));
                a2 = add2(a2, shfl_xor64(a2, m));
                a3 = add2(a3, shfl_xor64(a3, m));
            }
            if (slot == 0) {
                uint4 o = make_uint4(pkbf(a0), pkbf(a1), pkbf(a2), pkbf(a3));
                ((uint4*)g_z)[(size_t)v * 8 + q] = o;
            }
        } else {
            const uint2* hp = (const uint2*)h_in_v;   // 8 uint2 per 64B row
            u64 a0 = 0, a1 = 0;
            if (rp[n + 1] - e0 <= cap) {
                #pragma unroll 2
                for (int base = 0; base < total; base += 4) {
                    int j = base + slot - 1;
                    int rk = b0 + j; rk = rk > 0 ? rk : 0;
                    int sv = sidx[rk];
                    int idx = (j < 0) ? v : sv;
                    if (j < deg) {
                        uint2 r = __ldg(hp + (size_t)idx * 8 + q);
                        a0 = add2(a0, bf2f2(r.x));
                        a1 = add2(a1, bf2f2(r.y));
                    }
                }
            } else {
                for (int base = 0; base < total; base += 4) {
                    int j = base + slot - 1;
                    if (j < deg) {
                        int idx = (j < 0) ? v : __ldg(&g_csr[rp[n] + j]);
                        uint2 r = __ldg(hp + (size_t)idx * 8 + q);
                        a0 = add2(a0, bf2f2(r.x));
                        a1 = add2(a1, bf2f2(r.y));
                    }
                }
            }
            #pragma unroll
            for (int m = 8; m <= 16; m <<= 1) {
                a0 = add2(a0, shfl_xor64(a0, m));
                a1 = add2(a1, shfl_xor64(a1, m));
            }
            if (slot == 0) {
                uint2 o = make_uint2(pkbf(a0), pkbf(a1));
                ((uint2*)g_z)[(size_t)v * 16 + q] = o;   // 128B row stride, first 64B
            }
        }
    }
}

// ---------------- MLP via mma.sync (one CTA = 128 nodes, 8 warps x 16) ----------------
#define OFF_ZT   0
#define OFF_W1HI 18432
#define OFF_W1LO 27648
#define OFF_W2HI 36864
#define OFF_W2LO 46080
#define OFF_B1   55296
#define OFF_B2   55552
#define MLP_SMEM 55808

template <int KCH>
__device__ __forceinline__ void gemv16(uint32_t a_base, uint32_t whi, uint32_t wlo,
                                       float acc[8][4], int lane) {
    uint32_t a[KCH][4];
    uint32_t arow = a_base + (lane & 15) * 144 + ((lane >> 4) << 4);
    #pragma unroll
    for (int kc = 0; kc < KCH; kc++) ldsm_x4(a[kc], arow + kc * 32);
    uint32_t bro = (lane & 7) * 144 + ((lane & 8) ? 16 : 0);
    #pragma unroll
    for (int nc = 0; nc < 8; nc++) {
        #pragma unroll
        for (int i = 0; i < 4; i++) acc[nc][i] = 0.f;
        #pragma unroll
        for (int kc = 0; kc < KCH; kc++) {
            uint32_t bh[2], bl[2];
            ldsm_x2(bh, whi + bro + nc * 1152 + kc * 32);
            mma16816(acc[nc], a[kc], bh);
            ldsm_x2(bl, wlo + bro + nc * 1152 + kc * 32);
            mma16816(acc[nc], a[kc], bl);
        }
    }
}

template <int C, bool RELU_OUT, bool LAST>
__global__ void __launch_bounds__(256) mlp_mma(
    const uint4* __restrict__ w1hi, const uint4* __restrict__ w1lo,
    const uint4* __restrict__ w2hi, const uint4* __restrict__ w2lo,
    const float* __restrict__ b1, const float* __restrict__ b2,
    __nv_bfloat162* __restrict__ h_out)
{
    extern __shared__ char smem[];
    const uint32_t sb = smem_to_u32(smem);
    const int tid = threadIdx.x, wid = tid >> 5, lane = tid & 31;
    const int vbase = blockIdx.x * 128;
    const int wrow = wid * 16;

    // stage pre-split weights (vectorized; 512 uint4 per tile)
    for (int i = tid; i < 512; i += 256) {
        int f = i >> 3, j = i & 7;
        uint32_t d = f * 144 + j * 16;
        *(uint4*)(smem + OFF_W1HI + d) = __ldg(w1hi + i);
        *(uint4*)(smem + OFF_W1LO + d) = __ldg(w1lo + i);
        *(uint4*)(smem + OFF_W2HI + d) = __ldg(w2hi + i);
        *(uint4*)(smem + OFF_W2LO + d) = __ldg(w2lo + i);
    }
    if (tid < 64) {
        ((float*)(smem + OFF_B1))[tid] = __ldg(&b1[tid]);
        ((float*)(smem + OFF_B2))[tid] = __ldg(&b2[tid]);
    }

    // stage z rows
    constexpr int BPR = C / 8;   // uint4 blocks per row
    for (int i = tid; i < 128 * BPR; i += 256) {
        int row = i / BPR, j = i % BPR;
        int v = vbase + row;
        if (v < NN) {
            uint4 val = __ldg((const uint4*)g_z + (size_t)v * 8 + j);
            *(uint4*)(smem + OFF_ZT + row * 144 + j * 16) = val;
        }
    }
    __syncthreads();

    float acc[8][4];
    const uint32_t abase = sb + OFF_ZT + wrow * 144;

    // ---- GEMV1: t = relu(z @ W1 + b1) ----
    gemv16<C / 16>(abase, sb + OFF_W1HI, sb + OFF_W1LO, acc, lane);
    {
        const float* b1s = (const float*)(smem + OFF_B1);
        int r0off = (wrow + (lane >> 2)) * 144;
        int cb = 2 * (lane & 3);
        #pragma unroll
        for (int nc = 0; nc < 8; nc++) {
            int n0 = nc * 8 + cb;
            float bx = b1s[n0], by = b1s[n0 + 1];
            __nv_bfloat162 p0 = __float22bfloat162_rn(
                make_float2(fmaxf(acc[nc][0] + bx, 0.f), fmaxf(acc[nc][1] + by, 0.f)));
            __nv_bfloat162 p1 = __float22bfloat162_rn(
                make_float2(fmaxf(acc[nc][2] + bx, 0.f), fmaxf(acc[nc][3] + by, 0.f)));
            *(uint32_t*)(smem + OFF_ZT + r0off + n0 * 2) = *(uint32_t*)&p0;
            *(uint32_t*)(smem + OFF_ZT + r0off + 8 * 144 + n0 * 2) = *(uint32_t*)&p1;
        }
    }
    __syncwarp();   // t tile rows are warp-private

    // ---- GEMV2: o = t @ W2 + b2 ----
    gemv16<4>(abase, sb + OFF_W2HI, sb + OFF_W2LO, acc, lane);
    {
        const float* b2s = (const float*)(smem + OFF_B2);
        int r0 = wrow + (lane >> 2);
        int v0 = vbase + r0, v1 = v0 + 8;
        int cb = 2 * (lane & 3);
        #pragma unroll
        for (int nc = 0; nc < 8; nc++) {
            int n0 = nc * 8 + cb;
            float bx = b2s[n0], by = b2s[n0 + 1];
            float x0 = acc[nc][0] + bx, y0 = acc[nc][1] + by;
            float x1 = acc[nc][2] + bx, y1 = acc[nc][3] + by;
            if (LAST) {
                if (v0 < NN) *(float2*)(g_hF + (size_t)v0 * 64 + n0) = make_float2(x0, y0);
                if (v1 < NN) *(float2*)(g_hF + (size_t)v1 * 64 + n0) = make_float2(x1, y1);
            } else {
                if (RELU_OUT) {
                    x0 = fmaxf(x0, 0.f); y0 = fmaxf(y0, 0.f);
                    x1 = fmaxf(x1, 0.f); y1 = fmaxf(y1, 0.f);
                }
                __nv_bfloat162 p0 = __float22bfloat162_rn(make_float2(x0, y0));
                __nv_bfloat162 p1 = __float22bfloat162_rn(make_float2(x1, y1));
                if (v0 < NN) *((uint32_t*)h_out + (size_t)v0 * 32 + (n0 >> 1)) = *(uint32_t*)&p0;
                if (v1 < NN) *((uint32_t*)h_out + (size_t)v1 * 32 + (n0 >> 1)) = *(uint32_t*)&p1;
            }
        }
    }
}

// ---------------- pooling + final linear ----------------
__global__ void pool_kernel(const int* __restrict__ batch) {
    int w = (blockIdx.x * 256 + threadIdx.x) >> 5;
    int lane = threadIdx.x & 31;
    int v0 = w * 8;
    if (v0 >= NN) return;
    int vend = v0 + 8; if (vend > NN) vend = NN;
    int g0 = __ldg(&batch[v0]);
    if (__ldg(&batch[vend - 1]) == g0) {
        float2 s = make_float2(0.f, 0.f);
        for (int v = v0; v < vend; v++)
            s = f2add(s, *(const float2*)(g_hF + (size_t)v * 64 + 2 * lane));
        atomicAdd((float2*)&g_pool[g0 * 64 + 2 * lane], s);
    } else {
        for (int v = v0; v < vend; v++) {
            int g = __ldg(&batch[v]);
            float2 f = *(const float2*)(g_hF + (size_t)v * 64 + 2 * lane);
            atomicAdd((float2*)&g_pool[g * 64 + 2 * lane], f);
        }
    }
}

__global__ void final_kernel(const float* __restrict__ lin_w,
                             const float* __restrict__ lin_b,
                             float* __restrict__ out) {
    int gtid = blockIdx.x * blockDim.x + threadIdx.x;
    int g = gtid >> 5, lane = threadIdx.x & 31;
    if (g >= BB) return;
    float s = g_pool[g * 64 + lane] * __ldg(&lin_w[lane]) +
              g_pool[g * 64 + 32 + lane] * __ldg(&lin_w[32 + lane]);
    #pragma unroll
    for (int o = 16; o; o >>= 1) s += __shfl_xor_sync(0xffffffffu, s, o);
    if (lane == 0) {
        float cnt = (float)(g_end[g] - g_start[g]);
        out[g] = s / fmaxf(cnt, 1.f) + lin_b[0];
    }
}

// ---------------- launch ----------------
extern "C" void kernel_launch(void* const* d_in, const int* in_sizes, int n_in,
                              void* d_out, int out_size) {
    const float* x     = (const float*)d_in[0];
    const float* pos   = (const float*)d_in[1];
    const int*   ei    = (const int*)d_in[2];
    const int*   batch = (const int*)d_in[3];
    const float* W1f   = (const float*)d_in[4];
    const float* W1r   = (const float*)d_in[5];
    const float* b1    = (const float*)d_in[6];
    const float* W2    = (const float*)d_in[7];
    const float* b2    = (const float*)d_in[8];
    const float* lin_w = (const float*)d_in[9];
    const float* lin_b = (const float*)d_in[10];
    float* out = (float*)d_out;

    const int* src = ei;
    const int* dst = ei + EE;

    void *h0h, *hA, *hB, *whi, *wlo;
    cudaGetSymbolAddress(&h0h, g_h0h);
    cudaGetSymbolAddress(&hA, g_hA);
    cudaGetSymbolAddress(&hB, g_hB);
    cudaGetSymbolAddress(&whi, g_Whi);
    cudaGetSymbolAddress(&wlo, g_Wlo);

    cudaFuncSetAttribute((const void*)mlp_mma<32, true,  false>, cudaFuncAttributeMaxDynamicSharedMemorySize, MLP_SMEM);
    cudaFuncSetAttribute((const void*)mlp_mma<64, true,  false>, cudaFuncAttributeMaxDynamicSharedMemorySize, MLP_SMEM);
    cudaFuncSetAttribute((const void*)mlp_mma<64, false, true>,  cudaFuncAttributeMaxDynamicSharedMemorySize, MLP_SMEM);

    fused_init<<<(NN * 32 + 255) / 256, 256>>>(x, pos, batch, dst, W1f, W1r, W2);
    scanA_kernel<<<NSCAN_BLK, 1024>>>();
    scatter_fix<<<(EE + 255) / 256, 256>>>(src, dst);

    const int GB = (NN + 31) / 32;
    const int MB = (NN + 127) / 128;
    const int PB = ((NN / 8) * 32 + 255) / 256;

    // per-layer pre-split weight tile pointers (512 uint4 per tile)
    const uint4* WHI = (const uint4*)whi;
    const uint4* WLO = (const uint4*)wlo;

    gather_kernel<32><<<GB, 256>>>(h0h);
    mlp_mma<32, true, false><<<MB, 256, MLP_SMEM>>>(
        WHI + 0, WLO + 0, WHI + 512, WLO + 512, b1, b2, (__nv_bfloat162*)hA);

    void* cur = hA;
    void* nxt = hB;
    for (int l = 1; l < LL; l++) {
        const uint4* w1h = WHI + (size_t)(l * 2) * 512;
        const uint4* w1l = WLO + (size_t)(l * 2) * 512;
        const uint4* w2h = WHI + (size_t)(l * 2 + 1) * 512;
        const uint4* w2l = WLO + (size_t)(l * 2 + 1) * 512;
        gather_kernel<64><<<GB, 256>>>(cur);
        if (l < LL - 1) {
            mlp_mma<64, true, false><<<MB, 256, MLP_SMEM>>>(
                w1h, w1l, w2h, w2l, b1 + l * 64, b2 + l * 64, (__nv_bfloat162*)nxt);
            void* t = cur; cur = nxt; nxt = t;
        } else {
            mlp_mma<64, false, true><<<MB, 256, MLP_SMEM>>>(
                w1h, w1l, w2h, w2l, b1 + l * 64, b2 + l * 64, (__nv_bfloat162*)nxt);
        }
    }

    pool_kernel<<<PB, 256>>>(batch);
    final_kernel<<<(BB * 32 + 255) / 256, 256>>>(lin_w, lin_b, out);
}